// round 6
// baseline (speedup 1.0000x reference)
#include <cuda_runtime.h>
#include <cstdint>

// Fused int4-dequant + GEMM via mma.sync.m16n8k32.s8 (base ISA).
// Weights: int4 exact in int8; zero-point folded out as a linear correction
// against per-group row sums S[m,g]. Activations: 2-level int8 split
// x ~= sxl*(127*xh + xl), combined exactly in int32 before one fp32 dump
// per group with scale sxl[m]*sw[n,g].
//   y[m,n] = sum_g { sxl[m]*sw[n,g]*(127*Ah+Al) - sw*zp*S[m,g] } + bias[n]

#define MM 8192
#define NN 4096
#define KK 4096
#define GG 32
#define GSZ 128
#define KWORDS 512

#define BM 128
#define BN 128
#define PITCHB 144                       // 128B data + 16B pad per smem row
#define TILE_B (128 * PITCHB)            // 18432
#define S_OFF   (3 * TILE_B)             // 55296: S[m] 128 floats
#define SWZ_OFF (S_OFF + 512)            // 55808: (sw, -sw*zp) 128 float2
#define STAGE_B (SWZ_OFF + 1024)         // 56832
#define NSTG 2
#define SMEM_BYTES (NSTG * STAGE_B)      // 113664

// ---------------- device scratch ----------------
__device__ int8_t g_xh[(size_t)MM * KK];
__device__ int8_t g_xl[(size_t)MM * KK];
__device__ int8_t g_w8[(size_t)NN * KK];
__device__ float  g_sxl[MM];                 // per-row scale / 127
__device__ float  g_S[(size_t)GG * MM];      // group sums of x, [g][m]
__device__ float2 g_swz[(size_t)GG * NN];    // (sw, -sw*zp), [g][n]

__device__ __forceinline__ uint32_t smem_u32(const void* p) {
    return (uint32_t)__cvta_generic_to_shared(p);
}

#define LDSM_X4(r, addr) \
    asm volatile("ldmatrix.sync.aligned.m8n8.x4.shared.b16 {%0,%1,%2,%3}, [%4];" \
                 : "=r"((r)[0]), "=r"((r)[1]), "=r"((r)[2]), "=r"((r)[3]) \
                 : "r"(addr))

#define IMMA(d, a, b0, b1, c) \
    asm volatile("mma.sync.aligned.m16n8k32.row.col.s32.s8.s8.s32 " \
                 "{%0,%1,%2,%3}, {%4,%5,%6,%7}, {%8,%9}, {%10,%11,%12,%13};" \
                 : "=r"((d)[0]), "=r"((d)[1]), "=r"((d)[2]), "=r"((d)[3]) \
                 : "r"((a)[0]), "r"((a)[1]), "r"((a)[2]), "r"((a)[3]), \
                   "r"(b0), "r"(b1), \
                   "r"((c)[0]), "r"((c)[1]), "r"((c)[2]), "r"((c)[3]))

#define CP16(dst, src) \
    asm volatile("cp.async.cg.shared.global [%0], [%1], 16;" :: "r"(dst), "l"(src))

// ---------------- pass 0: quantize x (per-row 2-level int8) ----------------
__global__ void __launch_bounds__(256) quant_x_kernel(const float* __restrict__ x) {
    __shared__ float rmax[256];
    __shared__ float rsum[256];
    __shared__ float s_sx;
    const int m = blockIdx.x;
    const int t = threadIdx.x;
    const float* xr = x + (size_t)m * KK + t * 16;

    float v[16];
#pragma unroll
    for (int i = 0; i < 4; i++) ((float4*)v)[i] = ((const float4*)xr)[i];

    float amax = 0.f, ssum = 0.f;
#pragma unroll
    for (int i = 0; i < 16; i++) { amax = fmaxf(amax, fabsf(v[i])); ssum += v[i]; }
    rmax[t] = amax; rsum[t] = ssum;
    __syncthreads();
    for (int s = 128; s > 0; s >>= 1) {
        if (t < s) rmax[t] = fmaxf(rmax[t], rmax[t + s]);
        __syncthreads();
    }
    if (t == 0) {
        float am = rmax[0];
        float sx = (am > 0.f) ? am * (1.0f / 127.0f) : 1.0f;
        s_sx = sx;
        g_sxl[m] = sx * (1.0f / 127.0f);
    }
    __syncthreads();
    float sx = s_sx;
    float invsx = 1.0f / sx;
    float invsxl = 127.0f * invsx;

    int8_t h8[16], l8[16];
#pragma unroll
    for (int i = 0; i < 16; i++) {
        float h = rintf(v[i] * invsx);
        float r = v[i] - h * sx;
        float l = rintf(r * invsxl);
        h8[i] = (int8_t)(int)h;
        l8[i] = (int8_t)(int)l;
    }
    *(uint4*)(g_xh + (size_t)m * KK + t * 16) = *(const uint4*)h8;
    *(uint4*)(g_xl + (size_t)m * KK + t * 16) = *(const uint4*)l8;

    // exact group sums: group g = threads 8g..8g+7
    if (t < 32) {
        float s = 0.f;
#pragma unroll
        for (int j = 0; j < 8; j++) s += rsum[t * 8 + j];
        g_S[(size_t)t * MM + m] = s;
    }
}

// ---------------- pass 1: unpack int4 weights to int8 ----------------
__global__ void __launch_bounds__(256) prep_w_kernel(const int* __restrict__ qw) {
    int idx = blockIdx.x * 256 + threadIdx.x;     // word index over NN*KWORDS
    unsigned w = ((const unsigned*)qw)[idx];
    unsigned long long o = 0;
#pragma unroll
    for (int i = 0; i < 8; i++)
        o |= (unsigned long long)((w >> (4 * i)) & 0xF) << (8 * i);
    ((unsigned long long*)g_w8)[idx] = o;
}

// ---------------- pass 2: scale/zp table ----------------
__global__ void __launch_bounds__(256) swz_kernel(const float* __restrict__ sc,
                                                  const float* __restrict__ zp) {
    int idx = blockIdx.x * 256 + threadIdx.x;     // over NN*GG, layout [n][g]
    int n = idx >> 5;
    int g = idx & 31;
    float s = sc[idx];
    g_swz[(size_t)g * NN + n] = make_float2(s, -s * zp[idx]);
}

// ---------------- pass 3: int8 GEMM ----------------
__global__ void __launch_bounds__(256, 1)
gemm_s8_kernel(const float* __restrict__ bias, float* __restrict__ out) {
    extern __shared__ char sm[];
    const int tid = threadIdx.x;
    const int wid = tid >> 5;
    const int lane = tid & 31;
    const int warp_m = wid >> 2;       // 0..1 (64 rows)
    const int warp_n = wid & 3;        // 0..3 (32 cols)
    const int m0 = blockIdx.y * BM;
    const int n0 = blockIdx.x * BN;

    float accY[4][4][4];
#pragma unroll
    for (int i = 0; i < 4; i++)
#pragma unroll
        for (int j = 0; j < 4; j++)
#pragma unroll
            for (int r = 0; r < 4; r++) accY[i][j][r] = 0.f;

    // per-thread hoisted row scales (rows r, r+8 per mi)
    float sxl0[4], sxl1[4];
#pragma unroll
    for (int mi = 0; mi < 4; mi++) {
        int r = m0 + warp_m * 64 + mi * 16 + (lane >> 2);
        sxl0[mi] = g_sxl[r];
        sxl1[mi] = g_sxl[r + 8];
    }

    auto load_stage = [&](int g) {
        uint32_t stu = smem_u32(sm + (size_t)(g & 1) * STAGE_B);
        int kb = g * GSZ;
#pragma unroll
        for (int i = 0; i < 4; i++) {
            int idx = tid + i * 256;
            int row = idx >> 3, c = idx & 7;
            uint32_t d = stu + row * PITCHB + c * 16;
            CP16(d, g_xh + (size_t)(m0 + row) * KK + kb + c * 16);
            CP16(d + TILE_B, g_xl + (size_t)(m0 + row) * KK + kb + c * 16);
            CP16(d + 2 * TILE_B, g_w8 + (size_t)(n0 + row) * KK + kb + c * 16);
        }
        if (tid < 32)
            CP16(stu + S_OFF + tid * 16,
                 (const char*)(g_S + (size_t)g * MM + m0) + tid * 16);
        else if (tid < 96)
            CP16(stu + SWZ_OFF + (tid - 32) * 16,
                 (const char*)(g_swz + (size_t)g * NN + n0) + (tid - 32) * 16);
        asm volatile("cp.async.commit_group;");
    };

    load_stage(0);

    const uint32_t aoff = (uint32_t)((warp_m * 64 + (lane & 15)) * PITCHB + (lane >> 4) * 16);
    const uint32_t boff = (uint32_t)(2 * TILE_B + (warp_n * 32 + (lane & 15)) * PITCHB + (lane >> 4) * 16);
    const int zq[4] = {0, 0, 0, 0};

    for (int g = 0; g < GG; g++) {
        if (g + 1 < GG) {
            load_stage(g + 1);
            asm volatile("cp.async.wait_group 1;" ::: "memory");
        } else {
            asm volatile("cp.async.wait_group 0;" ::: "memory");
        }
        __syncthreads();

        char* st = sm + (size_t)(g & 1) * STAGE_B;
        uint32_t su = smem_u32(st);

        // B fragments for the whole group (n32 x k128)
        uint32_t bb[2][4][4];
#pragma unroll
        for (int ng = 0; ng < 2; ng++)
#pragma unroll
            for (int kc = 0; kc < 4; kc++)
                LDSM_X4(bb[ng][kc], su + boff + ng * 16 * PITCHB + kc * 32);

        int acc[4][4][4];
        // ---- xh pass ----
#pragma unroll
        for (int kc = 0; kc < 4; kc++) {
            uint32_t ah[4][4];
#pragma unroll
            for (int mi = 0; mi < 4; mi++)
                LDSM_X4(ah[mi], su + aoff + mi * 16 * PITCHB + kc * 32);
#pragma unroll
            for (int mi = 0; mi < 4; mi++)
#pragma unroll
                for (int nj = 0; nj < 4; nj++) {
                    uint32_t b0 = bb[nj >> 1][kc][nj & 1];
                    uint32_t b1 = bb[nj >> 1][kc][(nj & 1) + 2];
                    if (kc == 0) IMMA(acc[mi][nj], ah[mi], b0, b1, zq);
                    else         IMMA(acc[mi][nj], ah[mi], b0, b1, acc[mi][nj]);
                }
        }
        // ---- acc = 127*acc_h, then xl pass accumulates on top ----
#pragma unroll
        for (int mi = 0; mi < 4; mi++)
#pragma unroll
            for (int nj = 0; nj < 4; nj++)
#pragma unroll
                for (int r = 0; r < 4; r++) acc[mi][nj][r] *= 127;
#pragma unroll
        for (int kc = 0; kc < 4; kc++) {
            uint32_t al[4][4];
#pragma unroll
            for (int mi = 0; mi < 4; mi++)
                LDSM_X4(al[mi], su + TILE_B + aoff + mi * 16 * PITCHB + kc * 32);
#pragma unroll
            for (int mi = 0; mi < 4; mi++)
#pragma unroll
                for (int nj = 0; nj < 4; nj++) {
                    uint32_t b0 = bb[nj >> 1][kc][nj & 1];
                    uint32_t b1 = bb[nj >> 1][kc][(nj & 1) + 2];
                    IMMA(acc[mi][nj], al[mi], b0, b1, acc[mi][nj]);
                }
        }

        // ---- dump: accY += sw * (sxl * acc) + czpn * S ----
        float Sv0[4], Sv1[4];
#pragma unroll
        for (int mi = 0; mi < 4; mi++) {
            int r = warp_m * 64 + mi * 16 + (lane >> 2);
            Sv0[mi] = *(const float*)(st + S_OFF + r * 4);
            Sv1[mi] = *(const float*)(st + S_OFF + (r + 8) * 4);
        }
        float2 wz0[4], wz1[4];
#pragma unroll
        for (int nj = 0; nj < 4; nj++) {
            int c = warp_n * 32 + nj * 8 + (lane & 3) * 2;
            wz0[nj] = *(const float2*)(st + SWZ_OFF + c * 8);
            wz1[nj] = *(const float2*)(st + SWZ_OFF + (c + 1) * 8);
        }
#pragma unroll
        for (int mi = 0; mi < 4; mi++)
#pragma unroll
            for (int nj = 0; nj < 4; nj++) {
                float t0 = sxl0[mi] * (float)acc[mi][nj][0];
                float t1 = sxl0[mi] * (float)acc[mi][nj][1];
                float t2 = sxl1[mi] * (float)acc[mi][nj][2];
                float t3 = sxl1[mi] * (float)acc[mi][nj][3];
                accY[mi][nj][0] = fmaf(wz0[nj].x, t0, accY[mi][nj][0]);
                accY[mi][nj][0] = fmaf(wz0[nj].y, Sv0[mi], accY[mi][nj][0]);
                accY[mi][nj][1] = fmaf(wz1[nj].x, t1, accY[mi][nj][1]);
                accY[mi][nj][1] = fmaf(wz1[nj].y, Sv0[mi], accY[mi][nj][1]);
                accY[mi][nj][2] = fmaf(wz0[nj].x, t2, accY[mi][nj][2]);
                accY[mi][nj][2] = fmaf(wz0[nj].y, Sv1[mi], accY[mi][nj][2]);
                accY[mi][nj][3] = fmaf(wz1[nj].x, t3, accY[mi][nj][3]);
                accY[mi][nj][3] = fmaf(wz1[nj].y, Sv1[mi], accY[mi][nj][3]);
            }
        __syncthreads();
    }

    // ---------------- epilogue ----------------
    const int rb = lane >> 2;
    const int cb = (lane & 3) * 2;
#pragma unroll
    for (int mi = 0; mi < 4; mi++) {
        int m = m0 + warp_m * 64 + mi * 16 + rb;
#pragma unroll
        for (int nj = 0; nj < 4; nj++) {
            int n = n0 + warp_n * 32 + nj * 8 + cb;
            float2 bv = *(const float2*)(bias + n);
            float2 o0, o1;
            o0.x = accY[mi][nj][0] + bv.x;
            o0.y = accY[mi][nj][1] + bv.y;
            o1.x = accY[mi][nj][2] + bv.x;
            o1.y = accY[mi][nj][3] + bv.y;
            *(float2*)(out + (size_t)m * NN + n) = o0;
            *(float2*)(out + (size_t)(m + 8) * NN + n) = o1;
        }
    }
}

// ---------------- launch ----------------
extern "C" void kernel_launch(void* const* d_in, const int* in_sizes, int n_in,
                              void* d_out, int out_size) {
    const float* x    = (const float*)d_in[0];
    const int*   qw   = (const int*)d_in[1];
    const float* sc   = (const float*)d_in[2];
    const float* zp   = (const float*)d_in[3];
    const float* bias = (const float*)d_in[4];
    float* out = (float*)d_out;

    cudaFuncSetAttribute(gemm_s8_kernel,
                         cudaFuncAttributeMaxDynamicSharedMemorySize, SMEM_BYTES);

    quant_x_kernel<<<MM, 256>>>(x);
    prep_w_kernel<<<(NN * KWORDS) / 256, 256>>>(qw);
    swz_kernel<<<(NN * GG) / 256, 256>>>(sc, zp);
    gemm_s8_kernel<<<dim3(NN / BN, MM / BM), 256, SMEM_BYTES>>>(bias, out);
}

// round 7
// speedup vs baseline: 6.6116x; 6.6116x over previous
#include <cuda_runtime.h>
#include <cuda_fp16.h>
#include <cstdint>

// Fused int4-dequant + GEMM via mma.sync.m16n8k16 with **fp16 accumulators**
// (historically 2x issue rate vs f32-acc on fallback HMMA paths), promoting
// each k32 chunk into fp32 accumulators on the FMA pipe (overlaps tensor pipe).
// Error: fp16 x/w rounding (2.86e-4 measured) + chunk rounding ~5e-4 -> ~6.5e-4.

#define MM   8192
#define NN   4096
#define KK   4096
#define NGRP 32
#define KW   512

#define BM 128
#define BN 128
#define BK 32
#define NSTG 4
#define PITCH 40                       // halfs per smem row (64B data + 16B pad)
#define TILE_HALFS (128 * PITCH)       // 5120 halfs = 10240 B
#define STAGE_HALFS (2 * TILE_HALFS)
#define SMEM_BYTES (NSTG * STAGE_HALFS * 2)   // 81920
#define NKITER (KK / BK)               // 128

// ---------------- device scratch ----------------
__device__ __half g_xh[(size_t)MM * KK];
__device__ __half g_wh[(size_t)NN * KK];

__device__ __forceinline__ uint32_t smem_u32(const void* p) {
    return (uint32_t)__cvta_generic_to_shared(p);
}

#define LDSM_X4(r, addr) \
    asm volatile("ldmatrix.sync.aligned.m8n8.x4.shared.b16 {%0,%1,%2,%3}, [%4];" \
                 : "=r"((r)[0]), "=r"((r)[1]), "=r"((r)[2]), "=r"((r)[3]) \
                 : "r"(addr))

// fp16-accumulator MMA: D(2xf16x2) = A*B + C(2xf16x2)
#define MMA16816H(d0, d1, a, b0, b1, c0, c1) \
    asm volatile("mma.sync.aligned.m16n8k16.row.col.f16.f16.f16.f16 " \
                 "{%0,%1}, {%2,%3,%4,%5}, {%6,%7}, {%8,%9};" \
                 : "=r"(d0), "=r"(d1) \
                 : "r"((a)[0]), "r"((a)[1]), "r"((a)[2]), "r"((a)[3]), \
                   "r"(b0), "r"(b1), "r"(c0), "r"(c1))

#define CP16(dst, src) \
    asm volatile("cp.async.cg.shared.global [%0], [%1], 16;" :: "r"(dst), "l"(src))

// ---------------- pass 0: round x to fp16 ----------------
__global__ void __launch_bounds__(256) round_x_kernel(const float* __restrict__ x) {
    size_t i = ((size_t)blockIdx.x * 256 + threadIdx.x) * 8;
    float4 v0 = *(const float4*)(x + i);
    float4 v1 = *(const float4*)(x + i + 4);
    float f[8] = {v0.x, v0.y, v0.z, v0.w, v1.x, v1.y, v1.z, v1.w};
    __half h[8];
#pragma unroll
    for (int j = 0; j < 8; j++) h[j] = __float2half_rn(f[j]);
    *(uint4*)(g_xh + i) = *(const uint4*)h;
}

// ---------------- pass 1: dequant int4 weights -> fp16 ----------------
__global__ void __launch_bounds__(256) dequant_kernel(const int* __restrict__ qw,
                                                      const float* __restrict__ sc,
                                                      const float* __restrict__ zp) {
    int idx = blockIdx.x * 256 + threadIdx.x;
    int n = idx >> 9;
    int w = idx & 511;
    unsigned word = ((const unsigned*)qw)[idx];
    int g = w >> 4;
    float s = sc[n * NGRP + g];
    float z = zp[n * NGRP + g];
    __half o[8];
#pragma unroll
    for (int i = 0; i < 8; i++) {
        float q = (float)((word >> (4 * i)) & 0xF);
        o[i] = __float2half_rn(s * (q - z));
    }
    *(uint4*)(g_wh + (size_t)n * KK + w * 8) = *(const uint4*)o;
}

// ---------------- pass 2: GEMM ----------------
__global__ void __launch_bounds__(256, 2)
gemm_fp16_kernel(const float* __restrict__ bias, float* __restrict__ out) {
    extern __shared__ __half sm[];
    const int tid = threadIdx.x;
    const int wid = tid >> 5;
    const int lane = tid & 31;
    const int warp_m = wid >> 2;       // 0..1 -> 64 rows each
    const int warp_n = wid & 3;        // 0..3 -> 32 cols each
    const int m0 = blockIdx.y * BM;
    const int n0 = blockIdx.x * BN;

    float accY[4][4][4];
#pragma unroll
    for (int i = 0; i < 4; i++)
#pragma unroll
        for (int j = 0; j < 4; j++)
#pragma unroll
            for (int r = 0; r < 4; r++) accY[i][j][r] = 0.f;

    const int lrow = tid >> 2;         // 0..63
    const int lc = tid & 3;

    auto load_stage = [&](int s) {
        int buf = s & (NSTG - 1);
        uint32_t st = smem_u32(sm + buf * STAGE_HALFS);
        int k0 = s * BK;
        const __half* Ah = g_xh + (size_t)m0 * KK + k0;
        const __half* Bh = g_wh + (size_t)n0 * KK + k0;
#pragma unroll
        for (int i = 0; i < 2; i++) {
            int row = lrow + i * 64;
            uint32_t doff = (uint32_t)(row * PITCH + lc * 8) * 2;
            size_t soff = (size_t)row * KK + lc * 8;
            CP16(st + doff, Ah + soff);
            CP16(st + TILE_HALFS * 2 + doff, Bh + soff);
        }
        asm volatile("cp.async.commit_group;");
    };

    load_stage(0);
    load_stage(1);
    load_stage(2);

    const int lrow16 = lane & 15;
    const int lk8 = (lane >> 4) * 8;

    for (int s = 0; s < NKITER; s++) {
        asm volatile("cp.async.wait_group 2;" ::: "memory");
        __syncthreads();

        int buf = s & (NSTG - 1);
        uint32_t sA = smem_u32(sm + buf * STAGE_HALFS);
        uint32_t sB = sA + TILE_HALFS * 2;

        uint32_t d0[4][4], d1[4][4];   // fp16x2 accumulators for this k32 chunk

#pragma unroll
        for (int ks = 0; ks < 2; ks++) {
            uint32_t kb = (uint32_t)(ks * 16 + lk8) * 2;
            uint32_t ah[4][4], bb[2][4];
#pragma unroll
            for (int mi = 0; mi < 4; mi++) {
                uint32_t ro = (uint32_t)((warp_m * 64 + mi * 16 + lrow16) * PITCH) * 2 + kb;
                LDSM_X4(ah[mi], sA + ro);
            }
#pragma unroll
            for (int ng = 0; ng < 2; ng++) {
                uint32_t ro = (uint32_t)((warp_n * 32 + ng * 16 + lrow16) * PITCH) * 2 + kb;
                LDSM_X4(bb[ng], sB + ro);
            }
#pragma unroll
            for (int mi = 0; mi < 4; mi++) {
#pragma unroll
                for (int nj = 0; nj < 4; nj++) {
                    uint32_t b0 = bb[nj >> 1][nj & 1];
                    uint32_t b1 = bb[nj >> 1][(nj & 1) + 2];
                    if (ks == 0) {
                        MMA16816H(d0[mi][nj], d1[mi][nj], ah[mi], b0, b1, 0u, 0u);
                    } else {
                        MMA16816H(d0[mi][nj], d1[mi][nj], ah[mi], b0, b1,
                                  d0[mi][nj], d1[mi][nj]);
                    }
                }
            }
        }

        // promote chunk (fp16x2 -> fp32), overlaps next iter's tensor work
#pragma unroll
        for (int mi = 0; mi < 4; mi++) {
#pragma unroll
            for (int nj = 0; nj < 4; nj++) {
                float2 lo = __half22float2(*reinterpret_cast<__half2*>(&d0[mi][nj]));
                float2 hi = __half22float2(*reinterpret_cast<__half2*>(&d1[mi][nj]));
                accY[mi][nj][0] += lo.x;
                accY[mi][nj][1] += lo.y;
                accY[mi][nj][2] += hi.x;
                accY[mi][nj][3] += hi.y;
            }
        }

        if (s + 3 < NKITER) load_stage(s + 3);
    }

    // ---------------- epilogue ----------------
    const int rb = lane >> 2;
    const int cb = (lane & 3) * 2;
#pragma unroll
    for (int mi = 0; mi < 4; mi++) {
        int m = m0 + warp_m * 64 + mi * 16 + rb;
#pragma unroll
        for (int nj = 0; nj < 4; nj++) {
            int n = n0 + warp_n * 32 + nj * 8 + cb;
            float2 bv = *(const float2*)(bias + n);
            float2 o0, o1;
            o0.x = accY[mi][nj][0] + bv.x;
            o0.y = accY[mi][nj][1] + bv.y;
            o1.x = accY[mi][nj][2] + bv.x;
            o1.y = accY[mi][nj][3] + bv.y;
            *(float2*)(out + (size_t)m * NN + n) = o0;
            *(float2*)(out + (size_t)(m + 8) * NN + n) = o1;
        }
    }
}

// ---------------- launch ----------------
extern "C" void kernel_launch(void* const* d_in, const int* in_sizes, int n_in,
                              void* d_out, int out_size) {
    const float* x    = (const float*)d_in[0];
    const int*   qw   = (const int*)d_in[1];
    const float* sc   = (const float*)d_in[2];
    const float* zp   = (const float*)d_in[3];
    const float* bias = (const float*)d_in[4];
    float* out = (float*)d_out;

    cudaFuncSetAttribute(gemm_fp16_kernel,
                         cudaFuncAttributeMaxDynamicSharedMemorySize, SMEM_BYTES);

    round_x_kernel<<<(int)(((size_t)MM * KK) / 2048), 256>>>(x);
    dequant_kernel<<<(NN * KW) / 256, 256>>>(qw, sc, zp);
    gemm_fp16_kernel<<<dim3(NN / BN, MM / BM), 256, SMEM_BYTES>>>(bias, out);
}

// round 8
// speedup vs baseline: 7.4576x; 1.1280x over previous
#include <cuda_runtime.h>
#include <cuda_fp16.h>
#include <cstdint>

// Fused int4-dequant + GEMM via mma.sync.m16n8k16 f32-acc (base ISA; tcgen05
// unavailable through the harness's compute_103 PTX path).
// R8: BK=64 stages (half the barrier/wait overhead of BK=32), NSTG=3,
// prep fused into one kernel (also makes ncu -s5 land on the GEMM).

#define MM   8192
#define NN   4096
#define KK   4096
#define NGRP 32
#define KW   512

#define BM 128
#define BN 128
#define BK 64
#define NSTG 3
#define PITCH 72                        // halfs per row: 128B data + 16B pad
#define TILE_HALFS (128 * PITCH)        // 9216 halfs = 18432 B
#define STAGE_HALFS (2 * TILE_HALFS)    // A + B
#define SMEM_BYTES (NSTG * STAGE_HALFS * 2)   // 110592
#define NKITER (KK / BK)                // 64

// ---------------- device scratch ----------------
__device__ __half g_xh[(size_t)MM * KK];
__device__ __half g_wh[(size_t)NN * KK];

__device__ __forceinline__ uint32_t smem_u32(const void* p) {
    return (uint32_t)__cvta_generic_to_shared(p);
}

#define LDSM_X4(r, addr) \
    asm volatile("ldmatrix.sync.aligned.m8n8.x4.shared.b16 {%0,%1,%2,%3}, [%4];" \
                 : "=r"((r)[0]), "=r"((r)[1]), "=r"((r)[2]), "=r"((r)[3]) \
                 : "r"(addr))

#define MMA16816(c, a, b0, b1) \
    asm volatile("mma.sync.aligned.m16n8k16.row.col.f32.f16.f16.f32 " \
                 "{%0,%1,%2,%3}, {%4,%5,%6,%7}, {%8,%9}, {%0,%1,%2,%3};" \
                 : "+f"((c)[0]), "+f"((c)[1]), "+f"((c)[2]), "+f"((c)[3]) \
                 : "r"((a)[0]), "r"((a)[1]), "r"((a)[2]), "r"((a)[3]), \
                   "r"(b0), "r"(b1))

#define CP16(dst, src) \
    asm volatile("cp.async.cg.shared.global [%0], [%1], 16;" :: "r"(dst), "l"(src))

// ---------------- fused prep: round x + dequant W ----------------
#define XBLOCKS 16384                   // MM*KK / 2048
__global__ void __launch_bounds__(256) prep_kernel(const float* __restrict__ x,
                                                   const int* __restrict__ qw,
                                                   const float* __restrict__ sc,
                                                   const float* __restrict__ zp) {
    if (blockIdx.x < XBLOCKS) {
        size_t i = ((size_t)blockIdx.x * 256 + threadIdx.x) * 8;
        float4 v0 = *(const float4*)(x + i);
        float4 v1 = *(const float4*)(x + i + 4);
        float f[8] = {v0.x, v0.y, v0.z, v0.w, v1.x, v1.y, v1.z, v1.w};
        __half h[8];
#pragma unroll
        for (int j = 0; j < 8; j++) h[j] = __float2half_rn(f[j]);
        *(uint4*)(g_xh + i) = *(const uint4*)h;
    } else {
        int idx = (blockIdx.x - XBLOCKS) * 256 + threadIdx.x;   // word index
        int n = idx >> 9;
        int w = idx & 511;
        unsigned word = ((const unsigned*)qw)[idx];
        int g = w >> 4;
        float s = sc[n * NGRP + g];
        float z = zp[n * NGRP + g];
        __half o[8];
#pragma unroll
        for (int i = 0; i < 8; i++) {
            float q = (float)((word >> (4 * i)) & 0xF);
            o[i] = __float2half_rn(s * (q - z));
        }
        *(uint4*)(g_wh + (size_t)n * KK + w * 8) = *(const uint4*)o;
    }
}

// ---------------- GEMM ----------------
__global__ void __launch_bounds__(256, 2)
gemm_fp16_kernel(const float* __restrict__ bias, float* __restrict__ out) {
    extern __shared__ __half sm[];
    const int tid = threadIdx.x;
    const int wid = tid >> 5;
    const int lane = tid & 31;
    const int warp_m = wid >> 2;       // 0..1 -> 64 rows each
    const int warp_n = wid & 3;        // 0..3 -> 32 cols each
    const int m0 = blockIdx.y * BM;
    const int n0 = blockIdx.x * BN;

    float acc[4][4][4];
#pragma unroll
    for (int i = 0; i < 4; i++)
#pragma unroll
        for (int j = 0; j < 4; j++)
#pragma unroll
            for (int r = 0; r < 4; r++) acc[i][j][r] = 0.f;

    // loader: per tile 128 rows x 8 chunks of 16B; 2 tiles -> 8 chunks/thread
    const int lrow = tid >> 3;         // 0..31
    const int lc = tid & 7;            // 0..7

    auto load_stage = [&](int s) {
        int buf = s % NSTG;
        uint32_t st = smem_u32(sm + buf * STAGE_HALFS);
        int k0 = s * BK;
        const __half* Ah = g_xh + (size_t)m0 * KK + k0;
        const __half* Bh = g_wh + (size_t)n0 * KK + k0;
#pragma unroll
        for (int i = 0; i < 4; i++) {
            int row = lrow + i * 32;
            uint32_t doff = (uint32_t)(row * PITCH + lc * 8) * 2;
            size_t soff = (size_t)row * KK + lc * 8;
            CP16(st + doff, Ah + soff);
            CP16(st + TILE_HALFS * 2 + doff, Bh + soff);
        }
        asm volatile("cp.async.commit_group;");
    };

    load_stage(0);
    load_stage(1);

    const int lrow16 = lane & 15;
    const int lk16 = (lane >> 4) * 16;  // byte offset of 8-half group

    for (int s = 0; s < NKITER; s++) {
        asm volatile("cp.async.wait_group 1;" ::: "memory");
        __syncthreads();
        if (s + 2 < NKITER) load_stage(s + 2);

        int buf = s % NSTG;
        uint32_t sA = smem_u32(sm + buf * STAGE_HALFS);
        uint32_t sB = sA + TILE_HALFS * 2;

#pragma unroll
        for (int ks = 0; ks < 4; ks++) {
            uint32_t kb = (uint32_t)(ks * 32 + lk16);
            uint32_t ah[4][4], bb[2][4];
#pragma unroll
            for (int mi = 0; mi < 4; mi++) {
                uint32_t ro = (uint32_t)((warp_m * 64 + mi * 16 + lrow16) * PITCH) * 2 + kb;
                LDSM_X4(ah[mi], sA + ro);
            }
#pragma unroll
            for (int ng = 0; ng < 2; ng++) {
                uint32_t ro = (uint32_t)((warp_n * 32 + ng * 16 + lrow16) * PITCH) * 2 + kb;
                LDSM_X4(bb[ng], sB + ro);
            }
#pragma unroll
            for (int mi = 0; mi < 4; mi++) {
#pragma unroll
                for (int nj = 0; nj < 4; nj++) {
                    uint32_t b0 = bb[nj >> 1][nj & 1];
                    uint32_t b1 = bb[nj >> 1][(nj & 1) + 2];
                    MMA16816(acc[mi][nj], ah[mi], b0, b1);
                }
            }
        }
    }

    // ---------------- epilogue ----------------
    const int rb = lane >> 2;
    const int cb = (lane & 3) * 2;
#pragma unroll
    for (int mi = 0; mi < 4; mi++) {
        int m = m0 + warp_m * 64 + mi * 16 + rb;
#pragma unroll
        for (int nj = 0; nj < 4; nj++) {
            int n = n0 + warp_n * 32 + nj * 8 + cb;
            float2 bv = *(const float2*)(bias + n);
            float2 o0, o1;
            o0.x = acc[mi][nj][0] + bv.x;
            o0.y = acc[mi][nj][1] + bv.y;
            o1.x = acc[mi][nj][2] + bv.x;
            o1.y = acc[mi][nj][3] + bv.y;
            *(float2*)(out + (size_t)m * NN + n) = o0;
            *(float2*)(out + (size_t)(m + 8) * NN + n) = o1;
        }
    }
}

// ---------------- launch ----------------
extern "C" void kernel_launch(void* const* d_in, const int* in_sizes, int n_in,
                              void* d_out, int out_size) {
    const float* x    = (const float*)d_in[0];
    const int*   qw   = (const int*)d_in[1];
    const float* sc   = (const float*)d_in[2];
    const float* zp   = (const float*)d_in[3];
    const float* bias = (const float*)d_in[4];
    float* out = (float*)d_out;

    cudaFuncSetAttribute(gemm_fp16_kernel,
                         cudaFuncAttributeMaxDynamicSharedMemorySize, SMEM_BYTES);

    prep_kernel<<<XBLOCKS + (NN * KW) / 256, 256>>>(x, qw, sc, zp);
    gemm_fp16_kernel<<<dim3(NN / BN, MM / BM), 256, SMEM_BYTES>>>(bias, out);
}

// round 9
// speedup vs baseline: 7.7982x; 1.0457x over previous
#include <cuda_runtime.h>
#include <cuda_fp16.h>
#include <cstdint>

// Fused int4-dequant + GEMM via mma.sync.m16n8k16 f32-acc (base ISA; tcgen05
// unavailable through the harness's compute_103 PTX path).
// R9: register-level fragment double-buffering — prefetch the next k16-step's
// ldmatrix fragments before issuing the current step's HMMAs, hiding LDSM
// latency under tensor-pipe time (profile showed tensor=52.7%, rt=8 -> ~453us
// floor). Also fixes the tail wait_group race.

#define MM   8192
#define NN   4096
#define KK   4096
#define NGRP 32
#define KW   512

#define BM 128
#define BN 128
#define BK 64
#define NSTG 3
#define PITCH 72                        // halfs per row: 128B data + 16B pad
#define TILE_HALFS (128 * PITCH)        // 9216 halfs = 18432 B
#define STAGE_HALFS (2 * TILE_HALFS)    // A + B
#define SMEM_BYTES (NSTG * STAGE_HALFS * 2)   // 110592
#define NKITER (KK / BK)                // 64

// ---------------- device scratch ----------------
__device__ __half g_xh[(size_t)MM * KK];
__device__ __half g_wh[(size_t)NN * KK];

__device__ __forceinline__ uint32_t smem_u32(const void* p) {
    return (uint32_t)__cvta_generic_to_shared(p);
}

#define LDSM_X4(r, addr) \
    asm volatile("ldmatrix.sync.aligned.m8n8.x4.shared.b16 {%0,%1,%2,%3}, [%4];" \
                 : "=r"((r)[0]), "=r"((r)[1]), "=r"((r)[2]), "=r"((r)[3]) \
                 : "r"(addr))

#define MMA16816(c, a, b0, b1) \
    asm volatile("mma.sync.aligned.m16n8k16.row.col.f32.f16.f16.f32 " \
                 "{%0,%1,%2,%3}, {%4,%5,%6,%7}, {%8,%9}, {%0,%1,%2,%3};" \
                 : "+f"((c)[0]), "+f"((c)[1]), "+f"((c)[2]), "+f"((c)[3]) \
                 : "r"((a)[0]), "r"((a)[1]), "r"((a)[2]), "r"((a)[3]), \
                   "r"(b0), "r"(b1))

#define CP16(dst, src) \
    asm volatile("cp.async.cg.shared.global [%0], [%1], 16;" :: "r"(dst), "l"(src))

// ---------------- fused prep: round x + dequant W ----------------
#define XBLOCKS 16384                   // MM*KK / 2048
__global__ void __launch_bounds__(256) prep_kernel(const float* __restrict__ x,
                                                   const int* __restrict__ qw,
                                                   const float* __restrict__ sc,
                                                   const float* __restrict__ zp) {
    if (blockIdx.x < XBLOCKS) {
        size_t i = ((size_t)blockIdx.x * 256 + threadIdx.x) * 8;
        float4 v0 = *(const float4*)(x + i);
        float4 v1 = *(const float4*)(x + i + 4);
        float f[8] = {v0.x, v0.y, v0.z, v0.w, v1.x, v1.y, v1.z, v1.w};
        __half h[8];
#pragma unroll
        for (int j = 0; j < 8; j++) h[j] = __float2half_rn(f[j]);
        *(uint4*)(g_xh + i) = *(const uint4*)h;
    } else {
        int idx = (blockIdx.x - XBLOCKS) * 256 + threadIdx.x;   // word index
        int n = idx >> 9;
        int w = idx & 511;
        unsigned word = ((const unsigned*)qw)[idx];
        int g = w >> 4;
        float s = sc[n * NGRP + g];
        float z = zp[n * NGRP + g];
        __half o[8];
#pragma unroll
        for (int i = 0; i < 8; i++) {
            float q = (float)((word >> (4 * i)) & 0xF);
            o[i] = __float2half_rn(s * (q - z));
        }
        *(uint4*)(g_wh + (size_t)n * KK + w * 8) = *(const uint4*)o;
    }
}

// ---------------- GEMM ----------------
__global__ void __launch_bounds__(256, 2)
gemm_fp16_kernel(const float* __restrict__ bias, float* __restrict__ out) {
    extern __shared__ __half sm[];
    const int tid = threadIdx.x;
    const int wid = tid >> 5;
    const int lane = tid & 31;
    const int warp_m = wid >> 2;       // 0..1 -> 64 rows each
    const int warp_n = wid & 3;        // 0..3 -> 32 cols each
    const int m0 = blockIdx.y * BM;
    const int n0 = blockIdx.x * BN;

    float acc[4][4][4];
#pragma unroll
    for (int i = 0; i < 4; i++)
#pragma unroll
        for (int j = 0; j < 4; j++)
#pragma unroll
            for (int r = 0; r < 4; r++) acc[i][j][r] = 0.f;

    const int lrow = tid >> 3;         // 0..31
    const int lc = tid & 7;            // 0..7

    auto load_stage = [&](int s) {
        int buf = s % NSTG;
        uint32_t st = smem_u32(sm + buf * STAGE_HALFS);
        int k0 = s * BK;
        const __half* Ah = g_xh + (size_t)m0 * KK + k0;
        const __half* Bh = g_wh + (size_t)n0 * KK + k0;
#pragma unroll
        for (int i = 0; i < 4; i++) {
            int row = lrow + i * 32;
            uint32_t doff = (uint32_t)(row * PITCH + lc * 8) * 2;
            size_t soff = (size_t)row * KK + lc * 8;
            CP16(st + doff, Ah + soff);
            CP16(st + TILE_HALFS * 2 + doff, Bh + soff);
        }
        asm volatile("cp.async.commit_group;");
    };

    load_stage(0);
    load_stage(1);

    const int lrow16 = lane & 15;
    const int lk16 = (lane >> 4) * 16;  // byte offset of 8-half group

    // per-warp base offsets for fragment loads
    const uint32_t a_ro = (uint32_t)((warp_m * 64 + lrow16) * PITCH) * 2 + lk16;
    const uint32_t b_ro = (uint32_t)((warp_n * 32 + lrow16) * PITCH) * 2 + lk16;

    uint32_t ah[2][4][4], bb[2][2][4];

    for (int s = 0; s < NKITER; s++) {
        if (s + 1 < NKITER)
            asm volatile("cp.async.wait_group 1;" ::: "memory");
        else
            asm volatile("cp.async.wait_group 0;" ::: "memory");
        __syncthreads();

        int buf = s % NSTG;
        uint32_t sA = smem_u32(sm + buf * STAGE_HALFS);
        uint32_t sB = sA + TILE_HALFS * 2;

        // preload ks=0 fragments into buffer 0
#pragma unroll
        for (int mi = 0; mi < 4; mi++)
            LDSM_X4(ah[0][mi], sA + a_ro + (uint32_t)(mi * 16 * PITCH) * 2);
#pragma unroll
        for (int ng = 0; ng < 2; ng++)
            LDSM_X4(bb[0][ng], sB + b_ro + (uint32_t)(ng * 16 * PITCH) * 2);

        // issue next stage's gmem->smem copies (overlaps with this stage's math)
        if (s + 2 < NKITER) load_stage(s + 2);

#pragma unroll
        for (int ks = 0; ks < 4; ks++) {
            const int cur = ks & 1;
            const int nxt = cur ^ 1;
            if (ks < 3) {
                uint32_t kb = (uint32_t)((ks + 1) * 32);
#pragma unroll
                for (int mi = 0; mi < 4; mi++)
                    LDSM_X4(ah[nxt][mi], sA + a_ro + (uint32_t)(mi * 16 * PITCH) * 2 + kb);
#pragma unroll
                for (int ng = 0; ng < 2; ng++)
                    LDSM_X4(bb[nxt][ng], sB + b_ro + (uint32_t)(ng * 16 * PITCH) * 2 + kb);
            }
#pragma unroll
            for (int mi = 0; mi < 4; mi++) {
#pragma unroll
                for (int nj = 0; nj < 4; nj++) {
                    uint32_t b0 = bb[cur][nj >> 1][nj & 1];
                    uint32_t b1 = bb[cur][nj >> 1][(nj & 1) + 2];
                    MMA16816(acc[mi][nj], ah[cur][mi], b0, b1);
                }
            }
        }
    }

    // ---------------- epilogue ----------------
    const int rb = lane >> 2;
    const int cb = (lane & 3) * 2;
#pragma unroll
    for (int mi = 0; mi < 4; mi++) {
        int m = m0 + warp_m * 64 + mi * 16 + rb;
#pragma unroll
        for (int nj = 0; nj < 4; nj++) {
            int n = n0 + warp_n * 32 + nj * 8 + cb;
            float2 bv = *(const float2*)(bias + n);
            float2 o0, o1;
            o0.x = acc[mi][nj][0] + bv.x;
            o0.y = acc[mi][nj][1] + bv.y;
            o1.x = acc[mi][nj][2] + bv.x;
            o1.y = acc[mi][nj][3] + bv.y;
            *(float2*)(out + (size_t)m * NN + n) = o0;
            *(float2*)(out + (size_t)(m + 8) * NN + n) = o1;
        }
    }
}

// ---------------- launch ----------------
extern "C" void kernel_launch(void* const* d_in, const int* in_sizes, int n_in,
                              void* d_out, int out_size) {
    const float* x    = (const float*)d_in[0];
    const int*   qw   = (const int*)d_in[1];
    const float* sc   = (const float*)d_in[2];
    const float* zp   = (const float*)d_in[3];
    const float* bias = (const float*)d_in[4];
    float* out = (float*)d_out;

    cudaFuncSetAttribute(gemm_fp16_kernel,
                         cudaFuncAttributeMaxDynamicSharedMemorySize, SMEM_BYTES);

    prep_kernel<<<XBLOCKS + (NN * KW) / 256, 256>>>(x, qw, sc, zp);
    gemm_fp16_kernel<<<dim3(NN / BN, MM / BM), 256, SMEM_BYTES>>>(bias, out);
}